// round 9
// baseline (speedup 1.0000x reference)
#include <cuda_runtime.h>
#include <cuda_bf16.h>
#include <cstdint>

// GDLoss: elementwise Gaussian KL loss over [N,5] xywhr boxes. 176MB traffic.
// R9 = R6 pipeline geometry (3-stage ring, 256-box tiles, 1 sync/tile,
//      occ ~87%) + R8 slim math (trig-free determinants, single cos(2dr)
//      for the pred covariance, approx rcp/sqrt) + streaming output store.
// R5-R8 plateau: kernel ~30.5us, DRAM 67-72%, nothing saturated. This round
// pairs the best-measured pipeline with the smallest instruction body.

#define TAU_F   1.0f
#define EPS_F   1e-6f
#define BLK     256
#define STAGES  3
#define TILE_F  (BLK * 5)            // 1280 floats per tensor per tile
#define TILE_V4 (TILE_F / 4)         // 320 float4 per tensor per tile
#define GRID_P  1064                 // 7 blocks/SM * 152 SMs

__device__ __forceinline__ void cp_async16(unsigned smem_dst, const void* gmem_src) {
    asm volatile("cp.async.cg.shared.global [%0], [%1], 16;\n"
                 :: "r"(smem_dst), "l"(gmem_src));
}
__device__ __forceinline__ void cp_async4(unsigned smem_dst, const void* gmem_src) {
    asm volatile("cp.async.ca.shared.global [%0], [%1], 4;\n"
                 :: "r"(smem_dst), "l"(gmem_src));
}
__device__ __forceinline__ void cp_commit() {
    asm volatile("cp.async.commit_group;\n" ::: "memory");
}
template <int N>
__device__ __forceinline__ void cp_wait() {
    asm volatile("cp.async.wait_group %0;\n" :: "n"(N) : "memory");
}

__device__ __forceinline__ float rcp_fast(float x) {
    float r; asm("rcp.approx.f32 %0, %1;" : "=f"(r) : "f"(x)); return r;
}
__device__ __forceinline__ float sqrt_fast(float x) {
    float r; asm("sqrt.approx.f32 %0, %1;" : "=f"(r) : "f"(x)); return r;
}

// loss for one box pair:
//   det_t = tww*thh/16, det_p = pww*phh/16     (rotation-invariant, no trig)
//   t1num = ths(dx^2+dy^2) - thd(c2t(dx^2-dy^2) + 2 s2t dx dy)
//   n2num = 2(ths*phs - thd*phd*cos(2rt-2rp))
//   dis   = (t1num+n2num)*16/(tww*thh) + log((tww*thh)/(pww*phh)) - 2
__device__ __forceinline__ float gd_loss_one(
    float px, float py, float pw, float ph, float prr,
    float tx, float ty, float tw, float th, float trr)
{
    pw = fminf(fmaxf(pw, 1e-7f), 1e7f);
    ph = fminf(fmaxf(ph, 1e-7f), 1e7f);
    tw = fminf(fmaxf(tw, 1e-7f), 1e7f);
    th = fminf(fmaxf(th, 1e-7f), 1e7f);

    const float pww = pw * pw, phh = ph * ph;
    const float tww = tw * tw, thh = th * th;

    const float phs = 0.125f * (pww + phh);
    const float phd = 0.125f * (pww - phh);
    const float ths = 0.125f * (tww + thh);
    const float thd = 0.125f * (tww - thh);

    float s2t, c2t;
    __sincosf(2.0f * trr, &s2t, &c2t);
    const float cdd = __cosf(2.0f * (trr - prr));   // cos(2rt - 2rp)

    const float dx = px - tx;
    const float dy = py - ty;
    const float dx2 = dx * dx, dy2 = dy * dy;
    const float sum2 = dx2 + dy2, dif2 = dx2 - dy2;
    const float dxy = dx * dy;

    const float rot   = fmaf(c2t, dif2, 2.0f * s2t * dxy);
    const float t1num = fmaf(ths, sum2, -thd * rot);
    const float n2num = 2.0f * fmaf(-thd * phd, cdd, ths * phs);

    const float dtt = tww * thh;                    // 16*det_t
    const float dpp = pww * phh;                    // 16*det_p
    const float invdt16 = 16.0f * rcp_fast(dtt);
    const float logterm = __logf(dtt * rcp_fast(dpp));

    const float dis = fmaf(t1num + n2num, invdt16, logterm - 2.0f);
    const float kl = fmaxf(dis, EPS_F);
    return 1.0f - rcp_fast(TAU_F + sqrt_fast(kl));
}

__global__ void __launch_bounds__(BLK) gd_loss_kernel(
    const float* __restrict__ pred,
    const float* __restrict__ target,
    float* __restrict__ out,
    int n)
{
    __shared__ float sp[STAGES][TILE_F];
    __shared__ float st[STAGES][TILE_F];

    const int tid = threadIdx.x;
    const int numTiles = (n + BLK - 1) / BLK;      // <= 15625: int32-safe
    const int stride = gridDim.x;

    // Issue cp.async loads for tile t into ring slot. Always commits a group.
    auto issue = [&](int t, int slot) {
        if (t < numTiles) {
            const int tileBase = t * BLK;
            const int nb = n - tileBase;
            float* spb = sp[slot];
            float* stb = st[slot];
            const float* pbase = pred   + tileBase * 5;   // <= 20M: int32-safe
            const float* tbase = target + tileBase * 5;
            if (nb >= BLK) {
                const float4* p4 = (const float4*)pbase;
                const float4* t4 = (const float4*)tbase;
                #pragma unroll
                for (int j = 0; j < 2; ++j) {
                    const int i = tid + j * BLK;
                    if (i < TILE_V4) {
                        cp_async16((unsigned)__cvta_generic_to_shared(((float4*)spb) + i), p4 + i);
                        cp_async16((unsigned)__cvta_generic_to_shared(((float4*)stb) + i), t4 + i);
                    }
                }
            } else {
                const int nfloats = nb * 5;
                for (int i = tid; i < nfloats; i += BLK) {
                    cp_async4((unsigned)__cvta_generic_to_shared(spb + i), pbase + i);
                    cp_async4((unsigned)__cvta_generic_to_shared(stb + i), tbase + i);
                }
            }
        }
        cp_commit();
    };

    // Prologue: two tiles in flight.
    issue(blockIdx.x, 0);
    issue(blockIdx.x + stride, 1);

    int slot = 0;
    for (int tile = blockIdx.x; tile < numTiles; tile += stride) {
        cp_wait<1>();        // tile's data landed (next still in flight)
        __syncthreads();     // compute(k-1) finished everywhere -> buf(k-1) free
        int islot = slot + 2; if (islot >= STAGES) islot -= STAGES;   // == slot-1 mod 3
        issue(tile + 2 * stride, islot);

        const int tileBase = tile * BLK;
        const int nb = n - tileBase;

        if (tid < nb) {
            const float* spb = sp[slot];
            const float* stb = st[slot];
            const int b5 = tid * 5;   // stride-5 smem: gcd(5,32)=1, conflict-free
            const float loss = gd_loss_one(
                spb[b5 + 0], spb[b5 + 1], spb[b5 + 2], spb[b5 + 3], spb[b5 + 4],
                stb[b5 + 0], stb[b5 + 1], stb[b5 + 2], stb[b5 + 3], stb[b5 + 4]);
            __stcs(out + tileBase + tid, loss);   // streaming store: don't pollute L2
        }

        ++slot; if (slot >= STAGES) slot = 0;
    }
}

extern "C" void kernel_launch(void* const* d_in, const int* in_sizes, int n_in,
                              void* d_out, int out_size)
{
    const float* pred   = (const float*)d_in[0];
    const float* target = (const float*)d_in[1];
    // d_in[2] (weight) is unused by the reference computation (LOSS_WEIGHT=1).
    float* out = (float*)d_out;

    const int n = out_size;                      // N boxes; output is [N,1] floats
    const int numTiles = (n + BLK - 1) / BLK;    // 15625 for N=4M
    int grid = GRID_P;
    if (grid > numTiles) grid = numTiles;
    gd_loss_kernel<<<grid, BLK>>>(pred, target, out, n);
}